// round 10
// baseline (speedup 1.0000x reference)
#include <cuda_runtime.h>
#include <cuda_fp16.h>
#include <cstdint>

#define BB 2
#define SH 2048
#define SE 256
#define SS 2304
#define HH 16
#define DD 128
#define BM 64
#define BN 64
#define NKT (SS/BN)
#define NT 128

// smem (halves), XOR-swizzled, no padding:
// K buf: 64 rows x 128 halves (256B/row, 8x32B chunks, c^=row&7)
// V buf: 128 rows x 64 halves (128B/row, 4x32B chunks, c^=row&3)
#define KBUFH (64*128)              // 8192
#define VBUFH (128*64)              // 8192
#define VBASEH (2*KBUFH)            // 16384
#define SMEMH (VBASEH + 2*VBUFH)    // 32768 halves
#define SMEM_BYTES (SMEMH*2)        // 65536 B

#define PREP_BLKS ((BB*SS*HH*64)/256)          // 18432
#define VT_BLKS ((SS/32)*(DD/32)*BB*HH)        // 9216

#define ONESH2 0x3C003C00u          // half2(1.0, 1.0)

// Scratch: fp16, RoPE'd, concatenated, head-major, pair-permuted.
static __device__ __half g_Q[(size_t)BB*HH*SS*DD];   // [b,h][s][d']
static __device__ __half g_K[(size_t)BB*HH*SS*DD];   // [b,h][s][d']
static __device__ __half g_Vt[(size_t)BB*HH*SS*DD];  // [b,h][d][s']

__device__ __forceinline__ float ex2(float x) {
    float y; asm("ex2.approx.ftz.f32 %0, %1;" : "=f"(y) : "f"(x)); return y;
}
__device__ __forceinline__ uint32_t hex2(uint32_t x) {   // ex2 on packed half2
    uint32_t y; asm("ex2.approx.f16x2 %0, %1;" : "=r"(y) : "r"(x)); return y;
}
__device__ __forceinline__ uint32_t f2h2(float lo, float hi) {
    __half2 h = __floats2half2_rn(lo, hi);
    return *(uint32_t*)&h;
}
__device__ __forceinline__ void mma16(float* c, uint32_t a0, uint32_t a1, uint32_t a2,
                                      uint32_t a3, uint32_t b0, uint32_t b1) {
    asm volatile("mma.sync.aligned.m16n8k16.row.col.f32.f16.f16.f32 "
        "{%0,%1,%2,%3}, {%4,%5,%6,%7}, {%8,%9}, {%0,%1,%2,%3};"
        : "+f"(c[0]), "+f"(c[1]), "+f"(c[2]), "+f"(c[3])
        : "r"(a0), "r"(a1), "r"(a2), "r"(a3), "r"(b0), "r"(b1));
}
#define CPA16(dst, src) \
    asm volatile("cp.async.cg.shared.global [%0], [%1], 16;" \
        :: "r"((uint32_t)__cvta_generic_to_shared(dst)), "l"(src))
#define CP_COMMIT() asm volatile("cp.async.commit_group;" ::: "memory")
#define CP_WAIT0()  asm volatile("cp.async.wait_group 0;" ::: "memory")

// ---------------------------------------------------------------------------
// Fused pre-pass. Blocks [0, PREP_BLKS): concat + RoPE + fold scale*log2e into
// Q + fp16 + 16-group pair perm. Blocks [PREP_BLKS, +VT_BLKS): V transpose.
// ---------------------------------------------------------------------------
__global__ __launch_bounds__(256) void pre_kernel(
        const float* __restrict__ q,  const float* __restrict__ k,
        const float* __restrict__ v,
        const float* __restrict__ eq, const float* __restrict__ ek,
        const float* __restrict__ ev, const float* __restrict__ fr) {
    __shared__ float tile[32][33];
    int bx = blockIdx.x;
    int tid = threadIdx.x;

    if (bx < PREP_BLKS) {
        int idx = bx * 256 + tid;
        int dp = idx & 63;           // d-pair 0..63 (orig cols 2dp, 2dp+1)
        int t = idx >> 6;
        int h = t & 15;
        t >>= 4;
        int s = t % SS;
        int b = t / SS;

        const float *sq, *sk;
        if (s < SE) {
            size_t off = ((((size_t)b*SE + s)*HH + h)*DD) + 2*dp;
            sq = eq + off; sk = ek + off;
        } else {
            size_t off = ((((size_t)b*SH + (s - SE))*HH + h)*DD) + 2*dp;
            sq = q + off; sk = k + off;
        }
        const float* f = fr + ((size_t)s*64 + dp)*4;
        float f00 = f[0], f01 = f[1], f10 = f[2], f11 = f[3];

        int pos = ((dp >> 3) << 4) + 4*(dp & 3) + 2*((dp >> 2) & 1);
        size_t rowbase = (((size_t)(b*HH + h))*SS + s)*DD;
        const float qsc = 0.12751744530570984f;  // (1/sqrt(128)) * log2(e)

        float x0 = sq[0], x1 = sq[1];
        *(__half2*)(g_Q + rowbase + pos) =
            __floats2half2_rn((f00*x0 + f01*x1)*qsc, (f10*x0 + f11*x1)*qsc);
        x0 = sk[0]; x1 = sk[1];
        *(__half2*)(g_K + rowbase + pos) =
            __floats2half2_rn(f00*x0 + f01*x1, f10*x0 + f11*x1);
    } else {
        int vb = bx - PREP_BLKS;
        int bh = vb / ((SS/32)*(DD/32));
        int rem = vb % ((SS/32)*(DD/32));
        int s0 = (rem % (SS/32)) * 32;
        int d0 = (rem / (SS/32)) * 32;
        int b = bh >> 4, h = bh & 15;
        int tx = tid & 31, ty = tid >> 5;
        #pragma unroll
        for (int j = 0; j < 32; j += 8) {
            int s = s0 + ty + j;
            const float* src;
            if (s < SE) src = ev + (((size_t)b*SE + s)*HH + h)*DD;
            else        src = v + (((size_t)b*SH + (s - SE))*HH + h)*DD;
            tile[ty + j][tx] = src[d0 + tx];
        }
        __syncthreads();
        __half* dst = g_Vt + (size_t)bh*SS*DD;
        int sp = s0 + (tx & 16) + 4*((tx >> 1) & 3) + 2*((tx >> 3) & 1) + (tx & 1);
        #pragma unroll
        for (int j = 0; j < 32; j += 8) {
            int d = d0 + ty + j;
            dst[(size_t)d*SS + sp] = __float2half_rn(tile[tx][ty + j]);
        }
    }
}

// prefetch one KV tile (XOR-swizzled stores), NT=128 threads
#define PREFETCH_TILE(nkt) do {                                                \
    __half* kb2 = smh + ((nkt) & 1)*KBUFH;                                     \
    __half* vb2 = smh + VBASEH + ((nkt) & 1)*VBUFH;                            \
    const __half* kg2 = Kg + (size_t)(nkt)*BN*DD;                              \
    const __half* vg2 = Vtg + (nkt)*BN;                                        \
    _Pragma("unroll")                                                          \
    for (int it = 0; it < 8; it++) {                                           \
        int i = it*NT + tid;                                                   \
        int r = i >> 4, wi = i & 15;                                           \
        int off = r*128 + ((((wi >> 1) ^ r) & 7)*16) + (wi & 1)*8;             \
        CPA16(kb2 + off, kg2 + r*DD + wi*8);                                   \
    }                                                                          \
    _Pragma("unroll")                                                          \
    for (int it = 0; it < 8; it++) {                                           \
        int i = it*NT + tid;                                                   \
        int r = i >> 3, wi = i & 7;                                            \
        int off = r*64 + ((((wi >> 1) ^ r) & 3)*16) + (wi & 1)*8;              \
        CPA16(vb2 + off, vg2 + (size_t)r*SS + wi*8);                           \
    }                                                                          \
    CP_COMMIT();                                                               \
} while (0)

// ---------------------------------------------------------------------------
// Flash attention: 4 warps x 16 q-rows (BM=64), 3 CTAs/SM (3 warps/SMSP).
// fp16 m16n8k16, FA2 online max (vote-gated rescale), P register-resident,
// f16x2 exp, l via ones-MMA, XOR-swizzled unpadded smem.
// ---------------------------------------------------------------------------
__global__ __launch_bounds__(NT, 3) void attn_kernel(float* __restrict__ out) {
    extern __shared__ __half smh[];
    const int tid = threadIdx.x;
    const int w = tid >> 5, lane = tid & 31;
    const int gq = lane >> 2, qq = lane & 3;
    const int qt = blockIdx.x, h = blockIdx.y, b = blockIdx.z;
    const size_t bh = (size_t)(b*HH + h);
    const __half* Kg  = g_K  + bh*SS*DD;
    const __half* Vtg = g_Vt + bh*SS*DD;

    PREFETCH_TILE(0);

    // Q fragments held in registers for the whole kernel
    uint32_t qa[8][4];
    {
        const __half* Qg = g_Q + bh*SS*DD + ((size_t)qt*BM + w*16)*DD;
        const __half* r0 = Qg + (size_t)gq*DD + qq*4;
        const __half* r1 = r0 + 8*DD;
        #pragma unroll
        for (int kg = 0; kg < 8; kg++) {
            uint2 u = *(const uint2*)(r0 + kg*16);
            uint2 v2 = *(const uint2*)(r1 + kg*16);
            qa[kg][0] = u.x;  qa[kg][2] = u.y;
            qa[kg][1] = v2.x; qa[kg][3] = v2.y;
        }
    }

    float o[16][4];
    #pragma unroll
    for (int j = 0; j < 16; j++)
        #pragma unroll
        for (int e = 0; e < 4; e++) o[j][e] = 0.f;
    float ol[4] = {0.f, 0.f, 0.f, 0.f};   // l accumulator via ones-MMA
    float m0 = -1e9f, m1 = -1e9f;         // running row maxima (log2 domain)

    for (int kt = 0; kt < NKT; kt++) {
        const __half* kbuf = smh + (kt & 1)*KBUFH;
        const __half* vbuf = smh + VBASEH + (kt & 1)*VBUFH;

        CP_WAIT0();
        __syncthreads();
        if (kt + 1 < NKT) PREFETCH_TILE(kt + 1);

        // ---- S = Q . K^T : 8 k16-steps x 8 n-tiles ----
        float s[8][4];
        #pragma unroll
        for (int j = 0; j < 8; j++)
            #pragma unroll
            for (int e = 0; e < 4; e++) s[j][e] = 0.f;

        const __half* kB = kbuf + gq*128 + qq*4;
        #pragma unroll
        for (int kg = 0; kg < 8; kg++) {
            int coff = ((kg ^ gq) & 7) * 16;
            #pragma unroll
            for (int j = 0; j < 8; j++) {
                uint2 bb = *(const uint2*)(kB + j*1024 + coff);
                mma16(s[j], qa[kg][0], qa[kg][1], qa[kg][2], qa[kg][3],
                      bb.x, bb.y);
            }
        }

        // ---- online max update (quad-reduced), vote-gated rescale ----
        float tm0 = -1e9f, tm1 = -1e9f;
        #pragma unroll
        for (int j = 0; j < 8; j++) {
            tm0 = fmaxf(tm0, fmaxf(s[j][0], s[j][1]));
            tm1 = fmaxf(tm1, fmaxf(s[j][2], s[j][3]));
        }
        tm0 = fmaxf(tm0, __shfl_xor_sync(0xffffffffu, tm0, 1));
        tm0 = fmaxf(tm0, __shfl_xor_sync(0xffffffffu, tm0, 2));
        tm1 = fmaxf(tm1, __shfl_xor_sync(0xffffffffu, tm1, 1));
        tm1 = fmaxf(tm1, __shfl_xor_sync(0xffffffffu, tm1, 2));

        bool grew = (tm0 > m0) || (tm1 > m1);
        if (__any_sync(0xffffffffu, grew)) {
            float m0n = fmaxf(m0, tm0), m1n = fmaxf(m1, tm1);
            float a0 = ex2(m0 - m0n), a1 = ex2(m1 - m1n);
            m0 = m0n; m1 = m1n;
            ol[0] *= a0; ol[1] *= a0; ol[2] *= a1; ol[3] *= a1;
            #pragma unroll
            for (int j = 0; j < 16; j++) {
                o[j][0] *= a0; o[j][1] *= a0;
                o[j][2] *= a1; o[j][3] *= a1;
            }
        }

        // ---- p = ex2.f16x2(s - m); P stays in registers as PV A-frags ----
        uint32_t h01[8], h23[8];
        #pragma unroll
        for (int j = 0; j < 8; j++) {
            h01[j] = hex2(f2h2(s[j][0] - m0, s[j][1] - m0));
            h23[j] = hex2(f2h2(s[j][2] - m1, s[j][3] - m1));
        }

        // ---- O += P . V (and l += P . 1) : 4 k16-steps x (16+1) n-tiles ----
        const __half* vB = vbuf + gq*64 + qq*4;
        #pragma unroll
        for (int kg = 0; kg < 4; kg++) {
            uint32_t a0 = h01[2*kg],     a1 = h23[2*kg];
            uint32_t a2 = h01[2*kg + 1], a3 = h23[2*kg + 1];
            int coff = ((kg ^ gq) & 3) * 16;
            mma16(ol, a0, a1, a2, a3, ONESH2, ONESH2);
            #pragma unroll
            for (int j = 0; j < 16; j++) {
                uint2 vv = *(const uint2*)(vB + j*512 + coff);
                mma16(o[j], a0, a1, a2, a3, vv.x, vv.y);
            }
        }
    }

    // ---- epilogue (l comes straight from the ones-MMA accumulator) ----
    float inv0 = 1.f / ol[0], inv1 = 1.f / ol[2];

    int s0i = qt*BM + w*16 + gq;
    int s1i = s0i + 8;
    float *op0, *op1;
    if (s0i < SE) op0 = out + (size_t)BB*SH*HH*DD + (((size_t)b*SE + s0i)*HH + h)*DD;
    else          op0 = out + (((size_t)b*SH + (s0i - SE))*HH + h)*DD;
    if (s1i < SE) op1 = out + (size_t)BB*SH*HH*DD + (((size_t)b*SE + s1i)*HH + h)*DD;
    else          op1 = out + (((size_t)b*SH + (s1i - SE))*HH + h)*DD;

    #pragma unroll
    for (int j = 0; j < 16; j++) {
        float2 w0, w1;
        w0.x = o[j][0]*inv0; w0.y = o[j][1]*inv0;
        w1.x = o[j][2]*inv1; w1.y = o[j][3]*inv1;
        *(float2*)(op0 + j*8 + 2*qq) = w0;
        *(float2*)(op1 + j*8 + 2*qq) = w1;
    }
}

// ---------------------------------------------------------------------------
extern "C" void kernel_launch(void* const* d_in, const int* in_sizes, int n_in,
                              void* d_out, int out_size) {
    const float* q  = (const float*)d_in[0];
    const float* k  = (const float*)d_in[1];
    const float* v  = (const float*)d_in[2];
    const float* eq = (const float*)d_in[3];
    const float* ek = (const float*)d_in[4];
    const float* ev = (const float*)d_in[5];
    const float* fr = (const float*)d_in[6];
    float* out = (float*)d_out;

    pre_kernel<<<PREP_BLKS + VT_BLKS, 256>>>(q, k, v, eq, ek, ev, fr);

    static bool attr_set = false;
    if (!attr_set) {
        cudaFuncSetAttribute(attn_kernel,
                             cudaFuncAttributeMaxDynamicSharedMemorySize, SMEM_BYTES);
        attr_set = true;
    }
    dim3 grid(SS / BM, HH, BB);
    attn_kernel<<<grid, NT, SMEM_BYTES>>>(out);
}

// round 11
// speedup vs baseline: 1.0956x; 1.0956x over previous
#include <cuda_runtime.h>
#include <cuda_fp16.h>
#include <cstdint>

#define BB 2
#define SH 2048
#define SE 256
#define SS 2304
#define HH 16
#define DD 128
#define BM 128
#define BN 128
#define NKT (SS/BN)
#define NT 256

// smem (halves): K 128 rows x 144 (288B stride); V 128 rows x 144
#define KSTRH 144
#define VSTRH 144
#define KBUFH (128*KSTRH)           // 18432
#define VBUFH (128*VSTRH)           // 18432
#define VBASEH (2*KBUFH)            // 36864
#define SMEMH (VBASEH + 2*VBUFH)    // 73728 halves
#define SMEM_BYTES (SMEMH*2)        // 147456 B

#define PREP_BLKS ((BB*SS*HH*64)/256)          // 18432
#define VT_BLKS ((SS/32)*(DD/32)*BB*HH)        // 9216

// Scratch: fp16, RoPE'd, concatenated, head-major, pair-permuted.
static __device__ __half g_Q[(size_t)BB*HH*SS*DD];   // [b,h][s][d']
static __device__ __half g_K[(size_t)BB*HH*SS*DD];   // [b,h][s][d']
static __device__ __half g_Vt[(size_t)BB*HH*SS*DD];  // [b,h][d][s']

__device__ __forceinline__ float ex2(float x) {
    float y; asm("ex2.approx.ftz.f32 %0, %1;" : "=f"(y) : "f"(x)); return y;
}
__device__ __forceinline__ uint32_t f2h2(float lo, float hi) {
    __half2 h = __floats2half2_rn(lo, hi);
    return *(uint32_t*)&h;
}
__device__ __forceinline__ void mma16(float* c, uint32_t a0, uint32_t a1, uint32_t a2,
                                      uint32_t a3, uint32_t b0, uint32_t b1) {
    asm volatile("mma.sync.aligned.m16n8k16.row.col.f32.f16.f16.f32 "
        "{%0,%1,%2,%3}, {%4,%5,%6,%7}, {%8,%9}, {%0,%1,%2,%3};"
        : "+f"(c[0]), "+f"(c[1]), "+f"(c[2]), "+f"(c[3])
        : "r"(a0), "r"(a1), "r"(a2), "r"(a3), "r"(b0), "r"(b1));
}
#define CPA16(dst, src) \
    asm volatile("cp.async.cg.shared.global [%0], [%1], 16;" \
        :: "r"((uint32_t)__cvta_generic_to_shared(dst)), "l"(src))
#define CP_COMMIT() asm volatile("cp.async.commit_group;" ::: "memory")
#define CP_WAIT0()  asm volatile("cp.async.wait_group 0;" ::: "memory")

// ---------------------------------------------------------------------------
// Fused pre-pass. Blocks [0, PREP_BLKS): concat + RoPE + fold scale*log2e into
// Q + fp16 + 16-group pair perm. Blocks [PREP_BLKS, +VT_BLKS): V transpose.
// ---------------------------------------------------------------------------
__global__ __launch_bounds__(256) void pre_kernel(
        const float* __restrict__ q,  const float* __restrict__ k,
        const float* __restrict__ v,
        const float* __restrict__ eq, const float* __restrict__ ek,
        const float* __restrict__ ev, const float* __restrict__ fr) {
    __shared__ float tile[32][33];
    int bx = blockIdx.x;
    int tid = threadIdx.x;

    if (bx < PREP_BLKS) {
        int idx = bx * 256 + tid;
        int dp = idx & 63;           // d-pair 0..63 (orig cols 2dp, 2dp+1)
        int t = idx >> 6;
        int h = t & 15;
        t >>= 4;
        int s = t % SS;
        int b = t / SS;

        const float *sq, *sk;
        if (s < SE) {
            size_t off = ((((size_t)b*SE + s)*HH + h)*DD) + 2*dp;
            sq = eq + off; sk = ek + off;
        } else {
            size_t off = ((((size_t)b*SH + (s - SE))*HH + h)*DD) + 2*dp;
            sq = q + off; sk = k + off;
        }
        const float* f = fr + ((size_t)s*64 + dp)*4;
        float f00 = f[0], f01 = f[1], f10 = f[2], f11 = f[3];

        int pos = ((dp >> 3) << 4) + 4*(dp & 3) + 2*((dp >> 2) & 1);
        size_t rowbase = (((size_t)(b*HH + h))*SS + s)*DD;
        const float qsc = 0.12751744530570984f;  // (1/sqrt(128)) * log2(e)

        float x0 = sq[0], x1 = sq[1];
        *(__half2*)(g_Q + rowbase + pos) =
            __floats2half2_rn((f00*x0 + f01*x1)*qsc, (f10*x0 + f11*x1)*qsc);
        x0 = sk[0]; x1 = sk[1];
        *(__half2*)(g_K + rowbase + pos) =
            __floats2half2_rn(f00*x0 + f01*x1, f10*x0 + f11*x1);
    } else {
        int vb = bx - PREP_BLKS;
        int bh = vb / ((SS/32)*(DD/32));
        int rem = vb % ((SS/32)*(DD/32));
        int s0 = (rem % (SS/32)) * 32;
        int d0 = (rem / (SS/32)) * 32;
        int b = bh >> 4, h = bh & 15;
        int tx = tid & 31, ty = tid >> 5;
        #pragma unroll
        for (int j = 0; j < 32; j += 8) {
            int s = s0 + ty + j;
            const float* src;
            if (s < SE) src = ev + (((size_t)b*SE + s)*HH + h)*DD;
            else        src = v + (((size_t)b*SH + (s - SE))*HH + h)*DD;
            tile[ty + j][tx] = src[d0 + tx];
        }
        __syncthreads();
        __half* dst = g_Vt + (size_t)bh*SS*DD;
        int sp = s0 + (tx & 16) + 4*((tx >> 1) & 3) + 2*((tx >> 3) & 1) + (tx & 1);
        #pragma unroll
        for (int j = 0; j < 32; j += 8) {
            int d = d0 + ty + j;
            dst[(size_t)d*SS + sp] = __float2half_rn(tile[tx][ty + j]);
        }
    }
}

// prefetch one 128-row KV tile (NT=256 threads, 16x16B per thread)
#define PREFETCH_TILE(nkt) do {                                                \
    __half* kb2 = smh + ((nkt) & 1)*KBUFH;                                     \
    __half* vb2 = smh + VBASEH + ((nkt) & 1)*VBUFH;                            \
    const __half* kg2 = Kg + (size_t)(nkt)*BN*DD;                              \
    const __half* vg2 = Vtg + (nkt)*BN;                                        \
    _Pragma("unroll")                                                          \
    for (int it = 0; it < 8; it++) {                                           \
        int i = it*NT + tid;                                                   \
        int r = i >> 4, c = (i & 15) * 8;                                      \
        CPA16(kb2 + r*KSTRH + c, kg2 + r*DD + c);                              \
    }                                                                          \
    _Pragma("unroll")                                                          \
    for (int it = 0; it < 8; it++) {                                           \
        int i = it*NT + tid;                                                   \
        int r = i >> 4, c = (i & 15) * 8;                                      \
        CPA16(vb2 + r*VSTRH + c, vg2 + (size_t)r*SS + c);                      \
    }                                                                          \
    CP_COMMIT();                                                               \
} while (0)

// ---------------------------------------------------------------------------
// Flash attention: 8 warps x 16 q-rows, BN=128 (halved per-tile overheads),
// fp16 m16n8k16, FA2 online max (vote-gated rescale), P register-resident.
// ---------------------------------------------------------------------------
__global__ __launch_bounds__(NT, 1) void attn_kernel(float* __restrict__ out) {
    extern __shared__ __half smh[];
    const int tid = threadIdx.x;
    const int w = tid >> 5, lane = tid & 31;
    const int gq = lane >> 2, qq = lane & 3;
    const int qt = blockIdx.x, h = blockIdx.y, b = blockIdx.z;
    const size_t bh = (size_t)(b*HH + h);
    const __half* Kg  = g_K  + bh*SS*DD;
    const __half* Vtg = g_Vt + bh*SS*DD;

    PREFETCH_TILE(0);

    // Q fragments held in registers for the whole kernel
    uint32_t qa[8][4];
    {
        const __half* Qg = g_Q + bh*SS*DD + ((size_t)qt*BM + w*16)*DD;
        const __half* r0 = Qg + (size_t)gq*DD + qq*4;
        const __half* r1 = r0 + 8*DD;
        #pragma unroll
        for (int kg = 0; kg < 8; kg++) {
            uint2 u = *(const uint2*)(r0 + kg*16);
            uint2 v2 = *(const uint2*)(r1 + kg*16);
            qa[kg][0] = u.x;  qa[kg][2] = u.y;
            qa[kg][1] = v2.x; qa[kg][3] = v2.y;
        }
    }

    float o[16][4];
    #pragma unroll
    for (int j = 0; j < 16; j++)
        #pragma unroll
        for (int e = 0; e < 4; e++) o[j][e] = 0.f;
    float l0 = 0.f, l1 = 0.f;
    float m0 = -1e9f, m1 = -1e9f;   // running row maxima (log2 domain)

    for (int kt = 0; kt < NKT; kt++) {
        const __half* kbuf = smh + (kt & 1)*KBUFH;
        const __half* vbuf = smh + VBASEH + (kt & 1)*VBUFH;

        CP_WAIT0();
        __syncthreads();
        if (kt + 1 < NKT) PREFETCH_TILE(kt + 1);

        // ---- S = Q . K^T : 8 k16-steps x 16 n-tiles ----
        float s[16][4];
        #pragma unroll
        for (int j = 0; j < 16; j++)
            #pragma unroll
            for (int e = 0; e < 4; e++) s[j][e] = 0.f;

        const __half* kB = kbuf + gq*KSTRH + qq*4;
        #pragma unroll
        for (int kg = 0; kg < 8; kg++) {
            #pragma unroll
            for (int j = 0; j < 16; j++) {
                uint2 bb = *(const uint2*)(kB + j*8*KSTRH + kg*16);
                mma16(s[j], qa[kg][0], qa[kg][1], qa[kg][2], qa[kg][3],
                      bb.x, bb.y);
            }
        }

        // ---- online max update (quad-reduced), vote-gated rescale ----
        float tm0 = -1e9f, tm1 = -1e9f;
        #pragma unroll
        for (int j = 0; j < 16; j++) {
            tm0 = fmaxf(tm0, fmaxf(s[j][0], s[j][1]));
            tm1 = fmaxf(tm1, fmaxf(s[j][2], s[j][3]));
        }
        tm0 = fmaxf(tm0, __shfl_xor_sync(0xffffffffu, tm0, 1));
        tm0 = fmaxf(tm0, __shfl_xor_sync(0xffffffffu, tm0, 2));
        tm1 = fmaxf(tm1, __shfl_xor_sync(0xffffffffu, tm1, 1));
        tm1 = fmaxf(tm1, __shfl_xor_sync(0xffffffffu, tm1, 2));

        bool grew = (tm0 > m0) || (tm1 > m1);
        if (__any_sync(0xffffffffu, grew)) {
            float m0n = fmaxf(m0, tm0), m1n = fmaxf(m1, tm1);
            float a0 = ex2(m0 - m0n), a1 = ex2(m1 - m1n);
            m0 = m0n; m1 = m1n;
            l0 *= a0; l1 *= a1;
            #pragma unroll
            for (int j = 0; j < 16; j++) {
                o[j][0] *= a0; o[j][1] *= a0;
                o[j][2] *= a1; o[j][3] *= a1;
            }
        }

        // ---- p = exp2(s - m); P stays in registers as PV A-frags ----
        uint32_t h01[16], h23[16];
        #pragma unroll
        for (int j = 0; j < 16; j++) {
            float p0 = ex2(s[j][0] - m0);
            float p1 = ex2(s[j][1] - m0);
            float p2 = ex2(s[j][2] - m1);
            float p3 = ex2(s[j][3] - m1);
            l0 += p0 + p1;
            l1 += p2 + p3;
            h01[j] = f2h2(p0, p1);
            h23[j] = f2h2(p2, p3);
        }

        // ---- O += P . V : 8 k16-steps x 16 n-tiles ----
        const __half* vB = vbuf + gq*VSTRH + qq*4;
        #pragma unroll
        for (int kg = 0; kg < 8; kg++) {
            uint32_t a0 = h01[2*kg],     a1 = h23[2*kg];
            uint32_t a2 = h01[2*kg + 1], a3 = h23[2*kg + 1];
            #pragma unroll
            for (int j = 0; j < 16; j++) {
                uint2 vv = *(const uint2*)(vB + j*8*VSTRH + kg*16);
                mma16(o[j], a0, a1, a2, a3, vv.x, vv.y);
            }
        }
    }

    // ---- epilogue ----
    l0 += __shfl_xor_sync(0xffffffffu, l0, 1);
    l0 += __shfl_xor_sync(0xffffffffu, l0, 2);
    l1 += __shfl_xor_sync(0xffffffffu, l1, 1);
    l1 += __shfl_xor_sync(0xffffffffu, l1, 2);
    float inv0 = 1.f / l0, inv1 = 1.f / l1;

    int s0i = qt*BM + w*16 + gq;
    int s1i = s0i + 8;
    float *op0, *op1;
    if (s0i < SE) op0 = out + (size_t)BB*SH*HH*DD + (((size_t)b*SE + s0i)*HH + h)*DD;
    else          op0 = out + (((size_t)b*SH + (s0i - SE))*HH + h)*DD;
    if (s1i < SE) op1 = out + (size_t)BB*SH*HH*DD + (((size_t)b*SE + s1i)*HH + h)*DD;
    else          op1 = out + (((size_t)b*SH + (s1i - SE))*HH + h)*DD;

    #pragma unroll
    for (int j = 0; j < 16; j++) {
        float2 w0, w1;
        w0.x = o[j][0]*inv0; w0.y = o[j][1]*inv0;
        w1.x = o[j][2]*inv1; w1.y = o[j][3]*inv1;
        *(float2*)(op0 + j*8 + 2*qq) = w0;
        *(float2*)(op1 + j*8 + 2*qq) = w1;
    }
}

// ---------------------------------------------------------------------------
extern "C" void kernel_launch(void* const* d_in, const int* in_sizes, int n_in,
                              void* d_out, int out_size) {
    const float* q  = (const float*)d_in[0];
    const float* k  = (const float*)d_in[1];
    const float* v  = (const float*)d_in[2];
    const float* eq = (const float*)d_in[3];
    const float* ek = (const float*)d_in[4];
    const float* ev = (const float*)d_in[5];
    const float* fr = (const float*)d_in[6];
    float* out = (float*)d_out;

    pre_kernel<<<PREP_BLKS + VT_BLKS, 256>>>(q, k, v, eq, ek, ev, fr);

    static bool attr_set = false;
    if (!attr_set) {
        cudaFuncSetAttribute(attn_kernel,
                             cudaFuncAttributeMaxDynamicSharedMemorySize, SMEM_BYTES);
        attr_set = true;
    }
    dim3 grid(SS / BM, HH, BB);
    attn_kernel<<<grid, NT, SMEM_BYTES>>>(out);
}